// round 8
// baseline (speedup 1.0000x reference)
#include <cuda_runtime.h>
#include <cuda_fp16.h>
#include <cstdint>

// Problem constants (fixed by the dataset)
constexpr int N  = 50000;
constexpr int E  = 800000;
constexpr int R  = 3;
constexpr int FHID = 128;
constexpr int FOUT = 64;
constexpr int RN = R * N;
constexpr int RE = R * E;

constexpr int SCAN_BLK = 512;
constexpr int NSCAN = (RN + SCAN_BLK - 1) / SCAN_BLK;   // 293

// Scratch (device globals; no allocation allowed)
__device__ int    g_dego[RN];
__device__ int    g_degi[RN];
__device__ float  g_rso[RN];
__device__ float  g_rsi[RN];
__device__ int    g_off[RN + 1];
__device__ int    g_cur[RN];
__device__ int    g_part[RN];
__device__ int    g_bsum[SCAN_BLK];
__device__ int    g_eidx[RE];                       // CSR: src per (rel,dst)-bin
__device__ __half g_xw1h[(size_t)R * N * FHID];     // 38.4 MB (pre-scaled by rso)
__device__ __half g_acch[(size_t)N * FHID];         // 12.8 MB (layer-1 output, fp16)
__device__ __half g_xw2h[(size_t)R * N * FOUT];     // 19.2 MB (pre-scaled by rso)

// Side stream + events for capture-time fork (host objects, created at load).
static cudaStream_t g_s1 = nullptr;
static cudaEvent_t  g_evA = nullptr, g_evB = nullptr;
namespace {
struct StreamInit {
    StreamInit() {
        cudaStreamCreateWithFlags(&g_s1, cudaStreamNonBlocking);
        cudaEventCreateWithFlags(&g_evA, cudaEventDisableTiming);
        cudaEventCreateWithFlags(&g_evB, cudaEventDisableTiming);
    }
} g_streaminit;
}

// ---------------- degrees ----------------
__global__ void k_deg_count(const int* __restrict__ src, const int* __restrict__ dst) {
    int i = blockIdx.x * blockDim.x + threadIdx.x;
    if (i < RE) {
        int r = i / E;
        atomicAdd(&g_dego[r * N + src[i]], 1);
        atomicAdd(&g_degi[r * N + dst[i]], 1);
    }
}

__global__ void k_rso() {
    int i = blockIdx.x * blockDim.x + threadIdx.x;
    if (i < RN) {
        g_rso[i] = rsqrtf((float)(g_dego[i] + 1));
        g_rsi[i] = rsqrtf((float)(g_degi[i] + 1));
    }
}

// ---------------- CSR build ----------------
__global__ __launch_bounds__(SCAN_BLK) void k_scan1() {
    __shared__ int s[SCAN_BLK];
    int t = threadIdx.x;
    int i = blockIdx.x * SCAN_BLK + t;
    int v = (i < RN) ? g_degi[i] : 0;
    s[t] = v;
    __syncthreads();
#pragma unroll
    for (int off = 1; off < SCAN_BLK; off <<= 1) {
        int u = (t >= off) ? s[t - off] : 0;
        __syncthreads();
        s[t] += u;
        __syncthreads();
    }
    if (i < RN) g_part[i] = s[t];
    if (t == SCAN_BLK - 1) g_bsum[blockIdx.x] = s[t];
}

__global__ __launch_bounds__(SCAN_BLK) void k_scan23() {
    __shared__ int s[SCAN_BLK];
    int t = threadIdx.x, bid = blockIdx.x;
    s[t] = (t < bid && t < NSCAN) ? g_bsum[t] : 0;
    __syncthreads();
#pragma unroll
    for (int off = SCAN_BLK / 2; off > 0; off >>= 1) {
        if (t < off) s[t] += s[t + off];
        __syncthreads();
    }
    int blockpref = s[0];
    int i = bid * SCAN_BLK + t;
    if (i < RN) {
        int excl = g_part[i] - g_degi[i] + blockpref;
        g_off[i] = excl;
        g_cur[i] = excl;
    }
    if (i == 0) g_off[RN] = RE;
}

__global__ void k_fill(const int* __restrict__ src, const int* __restrict__ dst) {
    int i = blockIdx.x * blockDim.x + threadIdx.x;
    if (i < RE) {
        int r = i / E;
        int pos = atomicAdd(&g_cur[r * N + dst[i]], 1);
        g_eidx[pos] = src[i];
    }
}

// ---------------- tf32 helpers ----------------
__device__ __forceinline__ uint32_t f2tf(float f) {
    uint32_t u;
    asm("cvt.rna.tf32.f32 %0, %1;" : "=r"(u) : "f"(f));
    return u;
}

__device__ __forceinline__ void mma_tf32(float* d,
        uint32_t a0, uint32_t a1, uint32_t a2, uint32_t a3,
        uint32_t b0, uint32_t b1) {
    asm volatile(
        "mma.sync.aligned.m16n8k8.row.col.f32.tf32.tf32.f32 "
        "{%0,%1,%2,%3}, {%4,%5,%6,%7}, {%8,%9}, {%0,%1,%2,%3};"
        : "+f"(d[0]), "+f"(d[1]), "+f"(d[2]), "+f"(d[3])
        : "r"(a0), "r"(a1), "r"(a2), "r"(a3), "r"(b0), "r"(b1));
}

// accumulate 8 fp16 (uint4) into two float4
__device__ __forceinline__ void acc8(float4& a0, float4& a1, uint4 u) {
    float2 f;
    f = __half22float2(*reinterpret_cast<__half2*>(&u.x)); a0.x += f.x; a0.y += f.y;
    f = __half22float2(*reinterpret_cast<__half2*>(&u.y)); a0.z += f.x; a0.w += f.y;
    f = __half22float2(*reinterpret_cast<__half2*>(&u.z)); a1.x += f.x; a1.y += f.y;
    f = __half22float2(*reinterpret_cast<__half2*>(&u.w)); a1.z += f.x; a1.w += f.y;
}

__device__ __forceinline__ void red8(float4& a0, float4& a1, int m) {
    a0.x += __shfl_xor_sync(0xffffffffu, a0.x, m);
    a0.y += __shfl_xor_sync(0xffffffffu, a0.y, m);
    a0.z += __shfl_xor_sync(0xffffffffu, a0.z, m);
    a0.w += __shfl_xor_sync(0xffffffffu, a0.w, m);
    a1.x += __shfl_xor_sync(0xffffffffu, a1.x, m);
    a1.y += __shfl_xor_sync(0xffffffffu, a1.y, m);
    a1.z += __shfl_xor_sync(0xffffffffu, a1.z, m);
    a1.w += __shfl_xor_sync(0xffffffffu, a1.w, m);
}

// ---------------- tf32 GEMM F=128 (fp32 in) -> fp16 out, pre-scaled by rso ----------------
__global__ __launch_bounds__(256)
void gemm_tc128(const float* __restrict__ A, const float* __restrict__ Wb,
                __half* __restrict__ Cb, int nrows) {
    constexpr int K = 128, BK = 32;
    const int r = blockIdx.y;
    const float* B = Wb + (size_t)r * K * 128;
    __half* C = Cb + (size_t)r * nrows * 128;
    const int row0 = blockIdx.x * 128;
    const int t = threadIdx.x;
    const int warp = t >> 5, lane = t & 31;
    const int qr = lane >> 2, qc = lane & 3;
    const int wm = (warp & 3) * 32;
    const int wn = (warp >> 2) * 64;

    __shared__ uint32_t sA[128][BK + 4];
    __shared__ uint32_t sB[BK][128 + 8];

    float acc[2][8][4];
#pragma unroll
    for (int i = 0; i < 2; i++)
#pragma unroll
        for (int j = 0; j < 8; j++)
#pragma unroll
            for (int q = 0; q < 4; q++) acc[i][j][q] = 0.f;

    const int am = t >> 1;
    const int ak = (t & 1) * 16;
    const int bkr = t >> 3;
    const int bnc = (t & 7) * 16;

    for (int k0 = 0; k0 < K; k0 += BK) {
        {
            int grow = row0 + am;
#pragma unroll
            for (int q = 0; q < 4; q++) {
                float4 v = make_float4(0.f, 0.f, 0.f, 0.f);
                if (grow < nrows)
                    v = *(const float4*)(A + (size_t)grow * K + k0 + ak + q * 4);
                uint4 u = make_uint4(f2tf(v.x), f2tf(v.y), f2tf(v.z), f2tf(v.w));
                *(uint4*)&sA[am][ak + q * 4] = u;
            }
        }
        {
#pragma unroll
            for (int q = 0; q < 4; q++) {
                float4 v = *(const float4*)(B + (size_t)(k0 + bkr) * 128 + bnc + q * 4);
                uint4 u = make_uint4(f2tf(v.x), f2tf(v.y), f2tf(v.z), f2tf(v.w));
                *(uint4*)&sB[bkr][bnc + q * 4] = u;
            }
        }
        __syncthreads();
#pragma unroll
        for (int kf = 0; kf < 4; kf++) {
            const int kb = kf * 8;
            uint32_t a[2][4];
#pragma unroll
            for (int mf = 0; mf < 2; mf++) {
                int rr = wm + mf * 16 + qr;
                a[mf][0] = sA[rr][kb + qc];
                a[mf][1] = sA[rr + 8][kb + qc];
                a[mf][2] = sA[rr][kb + qc + 4];
                a[mf][3] = sA[rr + 8][kb + qc + 4];
            }
#pragma unroll
            for (int nf = 0; nf < 8; nf++) {
                int nn = wn + nf * 8 + qr;
                uint32_t b0 = sB[kb + qc][nn];
                uint32_t b1 = sB[kb + qc + 4][nn];
                mma_tf32(acc[0][nf], a[0][0], a[0][1], a[0][2], a[0][3], b0, b1);
                mma_tf32(acc[1][nf], a[1][0], a[1][1], a[1][2], a[1][3], b0, b1);
            }
        }
        __syncthreads();
    }
#pragma unroll
    for (int mf = 0; mf < 2; mf++) {
        int r0g = row0 + wm + mf * 16 + qr;
        int r1g = r0g + 8;
        float s0 = (r0g < nrows) ? g_rso[r * N + r0g] : 0.f;
        float s1 = (r1g < nrows) ? g_rso[r * N + r1g] : 0.f;
#pragma unroll
        for (int nf = 0; nf < 8; nf++) {
            int col = wn + nf * 8 + qc * 2;
            if (r0g < nrows)
                *(__half2*)(C + (size_t)r0g * 128 + col) =
                    __floats2half2_rn(acc[mf][nf][0] * s0, acc[mf][nf][1] * s0);
            if (r1g < nrows)
                *(__half2*)(C + (size_t)r1g * 128 + col) =
                    __floats2half2_rn(acc[mf][nf][2] * s1, acc[mf][nf][3] * s1);
        }
    }
}

// ---------------- tf32 GEMM F=64 (fp16 in, relu) -> fp16 out, pre-scaled by rso ---------
__global__ __launch_bounds__(256)
void gemm_tc64(const __half* __restrict__ A, const float* __restrict__ Wb,
               __half* __restrict__ Cb, int nrows) {
    constexpr int K = 128, BK = 32;
    const int r = blockIdx.y;
    const float* B = Wb + (size_t)r * K * 64;
    __half* C = Cb + (size_t)r * nrows * 64;
    const int row0 = blockIdx.x * 128;
    const int t = threadIdx.x;
    const int warp = t >> 5, lane = t & 31;
    const int qr = lane >> 2, qc = lane & 3;
    const int wm = (warp & 3) * 32;
    const int wn = (warp >> 2) * 32;

    __shared__ uint32_t sA[128][BK + 4];
    __shared__ uint32_t sB[BK][64 + 8];

    float acc[2][4][4];
#pragma unroll
    for (int i = 0; i < 2; i++)
#pragma unroll
        for (int j = 0; j < 4; j++)
#pragma unroll
            for (int q = 0; q < 4; q++) acc[i][j][q] = 0.f;

    const int am = t >> 1;
    const int ak = (t & 1) * 16;
    const int bkrow = t >> 3;
    const int bncol = (t & 7) * 8;

    for (int k0 = 0; k0 < K; k0 += BK) {
        {
            int grow = row0 + am;
            uint4 p0 = make_uint4(0, 0, 0, 0), p1 = p0;
            if (grow < nrows) {
                const __half* ar = A + (size_t)grow * K + k0 + ak;
                p0 = *(const uint4*)ar;
                p1 = *(const uint4*)(ar + 8);
            }
#pragma unroll
            for (int h = 0; h < 2; h++) {
                uint4 p = h ? p1 : p0;
                const uint32_t* pw = reinterpret_cast<const uint32_t*>(&p);
#pragma unroll
                for (int q = 0; q < 4; q++) {
                    float2 f = __half22float2(*reinterpret_cast<const __half2*>(&pw[q]));
                    sA[am][ak + h * 8 + q * 2 + 0] = f2tf(fmaxf(f.x, 0.f));
                    sA[am][ak + h * 8 + q * 2 + 1] = f2tf(fmaxf(f.y, 0.f));
                }
            }
        }
        {
#pragma unroll
            for (int q = 0; q < 2; q++) {
                float4 v = *(const float4*)(B + (size_t)(k0 + bkrow) * 64 + bncol + q * 4);
                uint4 u = make_uint4(f2tf(v.x), f2tf(v.y), f2tf(v.z), f2tf(v.w));
                *(uint4*)&sB[bkrow][bncol + q * 4] = u;
            }
        }
        __syncthreads();
#pragma unroll
        for (int kf = 0; kf < 4; kf++) {
            const int kb = kf * 8;
            uint32_t a[2][4];
#pragma unroll
            for (int mf = 0; mf < 2; mf++) {
                int rr = wm + mf * 16 + qr;
                a[mf][0] = sA[rr][kb + qc];
                a[mf][1] = sA[rr + 8][kb + qc];
                a[mf][2] = sA[rr][kb + qc + 4];
                a[mf][3] = sA[rr + 8][kb + qc + 4];
            }
#pragma unroll
            for (int nf = 0; nf < 4; nf++) {
                int nn = wn + nf * 8 + qr;
                uint32_t b0 = sB[kb + qc][nn];
                uint32_t b1 = sB[kb + qc + 4][nn];
                mma_tf32(acc[0][nf], a[0][0], a[0][1], a[0][2], a[0][3], b0, b1);
                mma_tf32(acc[1][nf], a[1][0], a[1][1], a[1][2], a[1][3], b0, b1);
            }
        }
        __syncthreads();
    }
#pragma unroll
    for (int mf = 0; mf < 2; mf++) {
        int r0g = row0 + wm + mf * 16 + qr;
        int r1g = r0g + 8;
        float s0 = (r0g < nrows) ? g_rso[r * N + r0g] : 0.f;
        float s1 = (r1g < nrows) ? g_rso[r * N + r1g] : 0.f;
#pragma unroll
        for (int nf = 0; nf < 4; nf++) {
            int col = wn + nf * 8 + qc * 2;
            if (r0g < nrows)
                *(__half2*)(C + (size_t)r0g * 64 + col) =
                    __floats2half2_rn(acc[mf][nf][0] * s0, acc[mf][nf][1] * s0);
            if (r1g < nrows)
                *(__half2*)(C + (size_t)r1g * 64 + col) =
                    __floats2half2_rn(acc[mf][nf][2] * s1, acc[mf][nf][3] * s1);
        }
    }
}

// ---------------- gather F=128: warp/node, 2 edges in flight (half-warp x uint4) --------
// out (fp16) = bias + sum_r rsi_r * (self + edges)
__global__ __launch_bounds__(256)
void k_gather128(const __half* __restrict__ xw, const float* __restrict__ b,
                 __half* __restrict__ out) {
    int w = (blockIdx.x * blockDim.x + threadIdx.x) >> 5;
    int lane = threadIdx.x & 31;
    if (w >= N) return;
    const int half = lane >> 4;
    const int c8 = (lane & 15) * 8;          // fp16 column base (8 cols per lane)

    // bias sum (same value in both halves)
    float4 tot0, tot1;
    {
        float4 x0 = *(const float4*)(b + 0 * FHID + c8);
        float4 x1 = *(const float4*)(b + 1 * FHID + c8);
        float4 x2 = *(const float4*)(b + 2 * FHID + c8);
        tot0 = make_float4(x0.x + x1.x + x2.x, x0.y + x1.y + x2.y,
                           x0.z + x1.z + x2.z, x0.w + x1.w + x2.w);
        float4 y0 = *(const float4*)(b + 0 * FHID + c8 + 4);
        float4 y1 = *(const float4*)(b + 1 * FHID + c8 + 4);
        float4 y2 = *(const float4*)(b + 2 * FHID + c8 + 4);
        tot1 = make_float4(y0.x + y1.x + y2.x, y0.y + y1.y + y2.y,
                           y0.z + y1.z + y2.z, y0.w + y1.w + y2.w);
    }
    // halves will be summed by xor16; bias must count once
    if (half == 1) {
        tot0 = make_float4(0.f, 0.f, 0.f, 0.f);
        tot1 = make_float4(0.f, 0.f, 0.f, 0.f);
    }

#pragma unroll
    for (int r = 0; r < R; r++) {
        const int bin = r * N + w;
        const __half* base = xw + (size_t)r * N * FHID + c8;
        float4 a0 = make_float4(0.f, 0.f, 0.f, 0.f), a1 = a0;
        int j0 = g_off[bin], j1 = g_off[bin + 1];
        int j = j0;
        for (; j + 8 <= j1; j += 8) {
            int s0 = __ldg(&g_eidx[j + 0 + half]);
            int s1 = __ldg(&g_eidx[j + 2 + half]);
            int s2 = __ldg(&g_eidx[j + 4 + half]);
            int s3 = __ldg(&g_eidx[j + 6 + half]);
            uint4 u0 = *(const uint4*)(base + (size_t)s0 * FHID);
            uint4 u1 = *(const uint4*)(base + (size_t)s1 * FHID);
            uint4 u2 = *(const uint4*)(base + (size_t)s2 * FHID);
            uint4 u3 = *(const uint4*)(base + (size_t)s3 * FHID);
            acc8(a0, a1, u0); acc8(a0, a1, u1);
            acc8(a0, a1, u2); acc8(a0, a1, u3);
        }
        for (; j + 2 <= j1; j += 2) {
            int s = __ldg(&g_eidx[j + half]);
            uint4 u = *(const uint4*)(base + (size_t)s * FHID);
            acc8(a0, a1, u);
        }
        if (j < j1 && half == 0) {
            int s = __ldg(&g_eidx[j]);
            uint4 u = *(const uint4*)(base + (size_t)s * FHID);
            acc8(a0, a1, u);
        }
        if (half == 0) {  // self-loop (row already carries rso)
            uint4 u = *(const uint4*)(base + (size_t)w * FHID);
            acc8(a0, a1, u);
        }
        red8(a0, a1, 16);
        float ri = g_rsi[bin];
        tot0.x = fmaf(ri, a0.x, tot0.x); tot0.y = fmaf(ri, a0.y, tot0.y);
        tot0.z = fmaf(ri, a0.z, tot0.z); tot0.w = fmaf(ri, a0.w, tot0.w);
        tot1.x = fmaf(ri, a1.x, tot1.x); tot1.y = fmaf(ri, a1.y, tot1.y);
        tot1.z = fmaf(ri, a1.z, tot1.z); tot1.w = fmaf(ri, a1.w, tot1.w);
    }
    // combine bias halves: tot currently identical across halves except bias zeroing;
    // after red8 on accumulators only, tot differs only in bias -> sum via xor16
    tot0.x += __shfl_xor_sync(0xffffffffu, 0.f, 16) ;  // no-op keep structure
    if (half == 0) {
        __half* row = out + (size_t)w * FHID + c8;
        uint4 o;
        *reinterpret_cast<__half2*>(&o.x) = __floats2half2_rn(tot0.x, tot0.y);
        *reinterpret_cast<__half2*>(&o.y) = __floats2half2_rn(tot0.z, tot0.w);
        *reinterpret_cast<__half2*>(&o.z) = __floats2half2_rn(tot1.x, tot1.y);
        *reinterpret_cast<__half2*>(&o.w) = __floats2half2_rn(tot1.z, tot1.w);
        *(uint4*)row = o;
    }
}

// ---------------- gather F=64: warp/node, 4 edges in flight (quarter-warp x uint4) ------
__global__ __launch_bounds__(256)
void k_gather64(const __half* __restrict__ xw, const float* __restrict__ b,
                float* __restrict__ out) {
    int w = (blockIdx.x * blockDim.x + threadIdx.x) >> 5;
    int lane = threadIdx.x & 31;
    if (w >= N) return;
    const int quarter = lane >> 3;
    const int c8 = (lane & 7) * 8;

    float4 tot0, tot1;
    {
        float4 x0 = *(const float4*)(b + 0 * FOUT + c8);
        float4 x1 = *(const float4*)(b + 1 * FOUT + c8);
        float4 x2 = *(const float4*)(b + 2 * FOUT + c8);
        tot0 = make_float4(x0.x + x1.x + x2.x, x0.y + x1.y + x2.y,
                           x0.z + x1.z + x2.z, x0.w + x1.w + x2.w);
        float4 y0 = *(const float4*)(b + 0 * FOUT + c8 + 4);
        float4 y1 = *(const float4*)(b + 1 * FOUT + c8 + 4);
        float4 y2 = *(const float4*)(b + 2 * FOUT + c8 + 4);
        tot1 = make_float4(y0.x + y1.x + y2.x, y0.y + y1.y + y2.y,
                           y0.z + y1.z + y2.z, y0.w + y1.w + y2.w);
    }
    if (quarter != 0) {
        tot0 = make_float4(0.f, 0.f, 0.f, 0.f);
        tot1 = make_float4(0.f, 0.f, 0.f, 0.f);
    }

#pragma unroll
    for (int r = 0; r < R; r++) {
        const int bin = r * N + w;
        const __half* base = xw + (size_t)r * N * FOUT + c8;
        float4 a0 = make_float4(0.f, 0.f, 0.f, 0.f), a1 = a0;
        int j0 = g_off[bin], j1 = g_off[bin + 1];
        int j = j0;
        for (; j + 8 <= j1; j += 8) {
            int s0 = __ldg(&g_eidx[j + quarter]);
            int s1 = __ldg(&g_eidx[j + 4 + quarter]);
            uint4 u0 = *(const uint4*)(base + (size_t)s0 * FOUT);
            uint4 u1 = *(const uint4*)(base + (size_t)s1 * FOUT);
            acc8(a0, a1, u0); acc8(a0, a1, u1);
        }
        for (; j + 4 <= j1; j += 4) {
            int s = __ldg(&g_eidx[j + quarter]);
            uint4 u = *(const uint4*)(base + (size_t)s * FOUT);
            acc8(a0, a1, u);
        }
        if (j + quarter < j1) {
            int s = __ldg(&g_eidx[j + quarter]);
            uint4 u = *(const uint4*)(base + (size_t)s * FOUT);
            acc8(a0, a1, u);
        }
        if (quarter == 0) {  // self-loop
            uint4 u = *(const uint4*)(base + (size_t)w * FOUT);
            acc8(a0, a1, u);
        }
        red8(a0, a1, 8);
        red8(a0, a1, 16);
        float ri = g_rsi[bin];
        tot0.x = fmaf(ri, a0.x, tot0.x); tot0.y = fmaf(ri, a0.y, tot0.y);
        tot0.z = fmaf(ri, a0.z, tot0.z); tot0.w = fmaf(ri, a0.w, tot0.w);
        tot1.x = fmaf(ri, a1.x, tot1.x); tot1.y = fmaf(ri, a1.y, tot1.y);
        tot1.z = fmaf(ri, a1.z, tot1.z); tot1.w = fmaf(ri, a1.w, tot1.w);
    }
    if (quarter == 0) {
        float* row = out + (size_t)w * FOUT + c8;
        *(float4*)row = tot0;
        *(float4*)(row + 4) = tot1;
    }
}

// ---------------- launch ----------------
extern "C" void kernel_launch(void* const* d_in, const int* in_sizes, int n_in,
                              void* d_out, int out_size) {
    const float* x   = (const float*)d_in[0];
    const int*   src = (const int*)d_in[1];
    const int*   dst = (const int*)d_in[2];
    const float* W1  = (const float*)d_in[3];
    const float* b1  = (const float*)d_in[4];
    const float* W2  = (const float*)d_in[5];
    const float* b2  = (const float*)d_in[6];
    float* out = (float*)d_out;

    __half *xw1, *xw2, *acc;
    int *dego, *degi;
    cudaGetSymbolAddress((void**)&xw1, g_xw1h);
    cudaGetSymbolAddress((void**)&acc, g_acch);
    cudaGetSymbolAddress((void**)&xw2, g_xw2h);
    cudaGetSymbolAddress((void**)&dego, g_dego);
    cudaGetSymbolAddress((void**)&degi, g_degi);

    const bool fork = (g_s1 != nullptr && g_evA != nullptr && g_evB != nullptr);
    cudaStream_t sb = fork ? g_s1 : (cudaStream_t)0;

    cudaMemsetAsync(dego, 0, RN * sizeof(int), 0);
    cudaMemsetAsync(degi, 0, RN * sizeof(int), 0);
    k_deg_count<<<(RE + 255) / 256, 256>>>(src, dst);

    if (fork) {
        cudaEventRecord(g_evA, 0);
        cudaStreamWaitEvent(sb, g_evA, 0);
    }
    k_scan1<<<NSCAN, SCAN_BLK, 0, sb>>>();
    k_scan23<<<NSCAN, SCAN_BLK, 0, sb>>>();
    k_fill<<<(RE + 255) / 256, 256, 0, sb>>>(src, dst);
    if (fork) cudaEventRecord(g_evB, sb);

    k_rso<<<(RN + 255) / 256, 256>>>();
    dim3 gg((N + 127) / 128, R);
    gemm_tc128<<<gg, 256>>>(x, W1, xw1, N);

    if (fork) cudaStreamWaitEvent((cudaStream_t)0, g_evB, 0);
    k_gather128<<<(N * 32 + 255) / 256, 256>>>(xw1, b1, acc);

    gemm_tc64<<<gg, 256>>>(acc, W2, xw2, N);
    k_gather64<<<(N * 32 + 255) / 256, 256>>>(xw2, b2, out);
}

// round 10
// speedup vs baseline: 1.1081x; 1.1081x over previous
#include <cuda_runtime.h>
#include <cuda_fp16.h>
#include <cstdint>

// Problem constants (fixed by the dataset)
constexpr int N  = 50000;
constexpr int E  = 800000;
constexpr int R  = 3;
constexpr int FHID = 128;
constexpr int FOUT = 64;
constexpr int RN = R * N;
constexpr int RE = R * E;

constexpr int SCAN_BLK = 512;
constexpr int NSCAN = (RN + SCAN_BLK - 1) / SCAN_BLK;   // 293

// Scratch (device globals; no allocation allowed)
__device__ int    g_dego[RN];
__device__ int    g_degi[RN];
__device__ float  g_rso[RN];
__device__ float  g_rsi[RN];
__device__ int    g_off[RN + 1];
__device__ int    g_cur[RN];
__device__ int    g_part[RN];
__device__ int    g_bsum[SCAN_BLK];
__device__ int    g_eidx[RE];                       // CSR: src per (rel,dst)-bin
__device__ __half g_xw1h[(size_t)R * N * FHID];     // 38.4 MB (pre-scaled by rso)
__device__ float  g_acc[(size_t)N * FHID];          // 25.6 MB
__device__ __half g_xw2h[(size_t)R * N * FOUT];     // 19.2 MB (pre-scaled by rso)

// Side stream + events (host objects, created at load).
static cudaStream_t g_s1 = nullptr;
static cudaEvent_t  g_evA = nullptr, g_evB = nullptr;
namespace {
struct StreamInit {
    StreamInit() {
        cudaStreamCreateWithFlags(&g_s1, cudaStreamNonBlocking);
        cudaEventCreateWithFlags(&g_evA, cudaEventDisableTiming);
        cudaEventCreateWithFlags(&g_evB, cudaEventDisableTiming);
    }
} g_streaminit;
}

// ---------------- degrees (split: dego on main, degi on side) ----------------
__global__ void k_dego(const int* __restrict__ src) {
    int i = blockIdx.x * blockDim.x + threadIdx.x;
    if (i < RE) atomicAdd(&g_dego[(i / E) * N + src[i]], 1);
}

__global__ void k_degi(const int* __restrict__ dst) {
    int i = blockIdx.x * blockDim.x + threadIdx.x;
    if (i < RE) atomicAdd(&g_degi[(i / E) * N + dst[i]], 1);
}

__global__ void k_rso() {
    int i = blockIdx.x * blockDim.x + threadIdx.x;
    if (i < RN) g_rso[i] = rsqrtf((float)(g_dego[i] + 1));
}

__global__ void k_rsi() {
    int i = blockIdx.x * blockDim.x + threadIdx.x;
    if (i < RN) g_rsi[i] = rsqrtf((float)(g_degi[i] + 1));
}

// ---------------- CSR build ----------------
__global__ __launch_bounds__(SCAN_BLK) void k_scan1() {
    __shared__ int s[SCAN_BLK];
    int t = threadIdx.x;
    int i = blockIdx.x * SCAN_BLK + t;
    int v = (i < RN) ? g_degi[i] : 0;
    s[t] = v;
    __syncthreads();
#pragma unroll
    for (int off = 1; off < SCAN_BLK; off <<= 1) {
        int u = (t >= off) ? s[t - off] : 0;
        __syncthreads();
        s[t] += u;
        __syncthreads();
    }
    if (i < RN) g_part[i] = s[t];
    if (t == SCAN_BLK - 1) g_bsum[blockIdx.x] = s[t];
}

__global__ __launch_bounds__(SCAN_BLK) void k_scan23() {
    __shared__ int s[SCAN_BLK];
    int t = threadIdx.x, bid = blockIdx.x;
    s[t] = (t < bid && t < NSCAN) ? g_bsum[t] : 0;
    __syncthreads();
#pragma unroll
    for (int off = SCAN_BLK / 2; off > 0; off >>= 1) {
        if (t < off) s[t] += s[t + off];
        __syncthreads();
    }
    int blockpref = s[0];
    int i = bid * SCAN_BLK + t;
    if (i < RN) {
        int excl = g_part[i] - g_degi[i] + blockpref;
        g_off[i] = excl;
        g_cur[i] = excl;
    }
    if (i == 0) g_off[RN] = RE;
}

__global__ void k_fill(const int* __restrict__ src, const int* __restrict__ dst) {
    int i = blockIdx.x * blockDim.x + threadIdx.x;
    if (i < RE) {
        int r = i / E;
        int pos = atomicAdd(&g_cur[r * N + dst[i]], 1);
        g_eidx[pos] = src[i];
    }
}

// ---------------- tf32 helpers ----------------
__device__ __forceinline__ uint32_t f2tf(float f) {
    uint32_t u;
    asm("cvt.rna.tf32.f32 %0, %1;" : "=r"(u) : "f"(f));
    return u;
}

__device__ __forceinline__ void mma_tf32(float* d,
        uint32_t a0, uint32_t a1, uint32_t a2, uint32_t a3,
        uint32_t b0, uint32_t b1) {
    asm volatile(
        "mma.sync.aligned.m16n8k8.row.col.f32.tf32.tf32.f32 "
        "{%0,%1,%2,%3}, {%4,%5,%6,%7}, {%8,%9}, {%0,%1,%2,%3};"
        : "+f"(d[0]), "+f"(d[1]), "+f"(d[2]), "+f"(d[3])
        : "r"(a0), "r"(a1), "r"(a2), "r"(a3), "r"(b0), "r"(b1));
}

// ---------------- tf32 GEMM F=128 -> fp16 out, pre-scaled by rso ----------------
template<bool RELU>
__global__ __launch_bounds__(256)
void gemm_tc128(const float* __restrict__ A, const float* __restrict__ Wb,
                __half* __restrict__ Cb, int nrows) {
    constexpr int K = 128, BK = 32;
    const int r = blockIdx.y;
    const float* B = Wb + (size_t)r * K * 128;
    __half* C = Cb + (size_t)r * nrows * 128;
    const int row0 = blockIdx.x * 128;
    const int t = threadIdx.x;
    const int warp = t >> 5, lane = t & 31;
    const int qr = lane >> 2, qc = lane & 3;
    const int wm = (warp & 3) * 32;
    const int wn = (warp >> 2) * 64;

    __shared__ uint32_t sA[128][BK + 4];
    __shared__ uint32_t sB[BK][128 + 8];

    float acc[2][8][4];
#pragma unroll
    for (int i = 0; i < 2; i++)
#pragma unroll
        for (int j = 0; j < 8; j++)
#pragma unroll
            for (int q = 0; q < 4; q++) acc[i][j][q] = 0.f;

    const int am = t >> 1;
    const int ak = (t & 1) * 16;
    const int bkr = t >> 3;
    const int bnc = (t & 7) * 16;

    for (int k0 = 0; k0 < K; k0 += BK) {
        {
            int grow = row0 + am;
#pragma unroll
            for (int q = 0; q < 4; q++) {
                float4 v = make_float4(0.f, 0.f, 0.f, 0.f);
                if (grow < nrows)
                    v = *(const float4*)(A + (size_t)grow * K + k0 + ak + q * 4);
                if (RELU) {
                    v.x = fmaxf(v.x, 0.f); v.y = fmaxf(v.y, 0.f);
                    v.z = fmaxf(v.z, 0.f); v.w = fmaxf(v.w, 0.f);
                }
                uint4 u = make_uint4(f2tf(v.x), f2tf(v.y), f2tf(v.z), f2tf(v.w));
                *(uint4*)&sA[am][ak + q * 4] = u;
            }
        }
        {
#pragma unroll
            for (int q = 0; q < 4; q++) {
                float4 v = *(const float4*)(B + (size_t)(k0 + bkr) * 128 + bnc + q * 4);
                uint4 u = make_uint4(f2tf(v.x), f2tf(v.y), f2tf(v.z), f2tf(v.w));
                *(uint4*)&sB[bkr][bnc + q * 4] = u;
            }
        }
        __syncthreads();
#pragma unroll
        for (int kf = 0; kf < 4; kf++) {
            const int kb = kf * 8;
            uint32_t a[2][4];
#pragma unroll
            for (int mf = 0; mf < 2; mf++) {
                int rr = wm + mf * 16 + qr;
                a[mf][0] = sA[rr][kb + qc];
                a[mf][1] = sA[rr + 8][kb + qc];
                a[mf][2] = sA[rr][kb + qc + 4];
                a[mf][3] = sA[rr + 8][kb + qc + 4];
            }
#pragma unroll
            for (int nf = 0; nf < 8; nf++) {
                int nn = wn + nf * 8 + qr;
                uint32_t b0 = sB[kb + qc][nn];
                uint32_t b1 = sB[kb + qc + 4][nn];
                mma_tf32(acc[0][nf], a[0][0], a[0][1], a[0][2], a[0][3], b0, b1);
                mma_tf32(acc[1][nf], a[1][0], a[1][1], a[1][2], a[1][3], b0, b1);
            }
        }
        __syncthreads();
    }
#pragma unroll
    for (int mf = 0; mf < 2; mf++) {
        int r0g = row0 + wm + mf * 16 + qr;
        int r1g = r0g + 8;
        float s0 = (r0g < nrows) ? g_rso[r * N + r0g] : 0.f;
        float s1 = (r1g < nrows) ? g_rso[r * N + r1g] : 0.f;
#pragma unroll
        for (int nf = 0; nf < 8; nf++) {
            int col = wn + nf * 8 + qc * 2;
            if (r0g < nrows)
                *(__half2*)(C + (size_t)r0g * 128 + col) =
                    __floats2half2_rn(acc[mf][nf][0] * s0, acc[mf][nf][1] * s0);
            if (r1g < nrows)
                *(__half2*)(C + (size_t)r1g * 128 + col) =
                    __floats2half2_rn(acc[mf][nf][2] * s1, acc[mf][nf][3] * s1);
        }
    }
}

// ---------------- tf32 GEMM F=64 -> fp16 out, pre-scaled by rso ----------------
template<bool RELU>
__global__ __launch_bounds__(256)
void gemm_tc64(const float* __restrict__ A, const float* __restrict__ Wb,
               __half* __restrict__ Cb, int nrows) {
    constexpr int K = 128, BK = 32;
    const int r = blockIdx.y;
    const float* B = Wb + (size_t)r * K * 64;
    __half* C = Cb + (size_t)r * nrows * 64;
    const int row0 = blockIdx.x * 128;
    const int t = threadIdx.x;
    const int warp = t >> 5, lane = t & 31;
    const int qr = lane >> 2, qc = lane & 3;
    const int wm = (warp & 3) * 32;
    const int wn = (warp >> 2) * 32;

    __shared__ uint32_t sA[128][BK + 4];
    __shared__ uint32_t sB[BK][64 + 8];

    float acc[2][4][4];
#pragma unroll
    for (int i = 0; i < 2; i++)
#pragma unroll
        for (int j = 0; j < 4; j++)
#pragma unroll
            for (int q = 0; q < 4; q++) acc[i][j][q] = 0.f;

    const int am = t >> 1;
    const int ak = (t & 1) * 16;
    const int bkrow = t >> 3;
    const int bncol = (t & 7) * 8;

    for (int k0 = 0; k0 < K; k0 += BK) {
        {
            int grow = row0 + am;
#pragma unroll
            for (int q = 0; q < 4; q++) {
                float4 v = make_float4(0.f, 0.f, 0.f, 0.f);
                if (grow < nrows)
                    v = *(const float4*)(A + (size_t)grow * K + k0 + ak + q * 4);
                if (RELU) {
                    v.x = fmaxf(v.x, 0.f); v.y = fmaxf(v.y, 0.f);
                    v.z = fmaxf(v.z, 0.f); v.w = fmaxf(v.w, 0.f);
                }
                uint4 u = make_uint4(f2tf(v.x), f2tf(v.y), f2tf(v.z), f2tf(v.w));
                *(uint4*)&sA[am][ak + q * 4] = u;
            }
        }
        {
#pragma unroll
            for (int q = 0; q < 2; q++) {
                float4 v = *(const float4*)(B + (size_t)(k0 + bkrow) * 64 + bncol + q * 4);
                uint4 u = make_uint4(f2tf(v.x), f2tf(v.y), f2tf(v.z), f2tf(v.w));
                *(uint4*)&sB[bkrow][bncol + q * 4] = u;
            }
        }
        __syncthreads();
#pragma unroll
        for (int kf = 0; kf < 4; kf++) {
            const int kb = kf * 8;
            uint32_t a[2][4];
#pragma unroll
            for (int mf = 0; mf < 2; mf++) {
                int rr = wm + mf * 16 + qr;
                a[mf][0] = sA[rr][kb + qc];
                a[mf][1] = sA[rr + 8][kb + qc];
                a[mf][2] = sA[rr][kb + qc + 4];
                a[mf][3] = sA[rr + 8][kb + qc + 4];
            }
#pragma unroll
            for (int nf = 0; nf < 4; nf++) {
                int nn = wn + nf * 8 + qr;
                uint32_t b0 = sB[kb + qc][nn];
                uint32_t b1 = sB[kb + qc + 4][nn];
                mma_tf32(acc[0][nf], a[0][0], a[0][1], a[0][2], a[0][3], b0, b1);
                mma_tf32(acc[1][nf], a[1][0], a[1][1], a[1][2], a[1][3], b0, b1);
            }
        }
        __syncthreads();
    }
#pragma unroll
    for (int mf = 0; mf < 2; mf++) {
        int r0g = row0 + wm + mf * 16 + qr;
        int r1g = r0g + 8;
        float s0 = (r0g < nrows) ? g_rso[r * N + r0g] : 0.f;
        float s1 = (r1g < nrows) ? g_rso[r * N + r1g] : 0.f;
#pragma unroll
        for (int nf = 0; nf < 4; nf++) {
            int col = wn + nf * 8 + qc * 2;
            if (r0g < nrows)
                *(__half2*)(C + (size_t)r0g * 64 + col) =
                    __floats2half2_rn(acc[mf][nf][0] * s0, acc[mf][nf][1] * s0);
            if (r1g < nrows)
                *(__half2*)(C + (size_t)r1g * 64 + col) =
                    __floats2half2_rn(acc[mf][nf][2] * s1, acc[mf][nf][3] * s1);
        }
    }
}

// ---------------- fused gather + selfloop + bias, F=128 (fp16 pre-scaled, unroll 8) -----
__global__ __launch_bounds__(256)
void k_gather128(const __half* __restrict__ xw, const float* __restrict__ b,
                 float* __restrict__ out) {
    int w = (blockIdx.x * blockDim.x + threadIdx.x) >> 5;
    int lane = threadIdx.x & 31;
    if (w >= N) return;
    int c = lane * 4;

    float4 b0 = *(const float4*)(b + 0 * FHID + c);
    float4 b1 = *(const float4*)(b + 1 * FHID + c);
    float4 b2 = *(const float4*)(b + 2 * FHID + c);
    float4 tot = make_float4(b0.x + b1.x + b2.x, b0.y + b1.y + b2.y,
                             b0.z + b1.z + b2.z, b0.w + b1.w + b2.w);

#pragma unroll
    for (int r = 0; r < R; r++) {
        const int bin = r * N + w;
        const __half* base = xw + (size_t)r * N * FHID;
        float4 a = make_float4(0.f, 0.f, 0.f, 0.f);
        int j0 = g_off[bin], j1 = g_off[bin + 1];
        int j = j0;
        for (; j + 8 <= j1; j += 8) {
            int s[8];
#pragma unroll
            for (int p = 0; p < 8; p++) s[p] = __ldg(&g_eidx[j + p]);
            uint2 u[8];
#pragma unroll
            for (int p = 0; p < 8; p++)
                u[p] = *(const uint2*)(base + (size_t)s[p] * FHID + c);
#pragma unroll
            for (int p = 0; p < 8; p++) {
                float2 f0 = __half22float2(*reinterpret_cast<__half2*>(&u[p].x));
                float2 f1 = __half22float2(*reinterpret_cast<__half2*>(&u[p].y));
                a.x += f0.x; a.y += f0.y; a.z += f1.x; a.w += f1.y;
            }
        }
        for (; j < j1; j++) {
            int s = __ldg(&g_eidx[j]);
            uint2 u = *(const uint2*)(base + (size_t)s * FHID + c);
            float2 f0 = __half22float2(*reinterpret_cast<__half2*>(&u.x));
            float2 f1 = __half22float2(*reinterpret_cast<__half2*>(&u.y));
            a.x += f0.x; a.y += f0.y; a.z += f1.x; a.w += f1.y;
        }
        // self-loop: pre-scaled row already carries rso[w]
        {
            uint2 u = *(const uint2*)(base + (size_t)w * FHID + c);
            float2 f0 = __half22float2(*reinterpret_cast<__half2*>(&u.x));
            float2 f1 = __half22float2(*reinterpret_cast<__half2*>(&u.y));
            a.x += f0.x; a.y += f0.y; a.z += f1.x; a.w += f1.y;
        }
        float ri = g_rsi[bin];
        tot.x = fmaf(ri, a.x, tot.x); tot.y = fmaf(ri, a.y, tot.y);
        tot.z = fmaf(ri, a.z, tot.z); tot.w = fmaf(ri, a.w, tot.w);
    }
    *(float4*)(out + (size_t)w * FHID + c) = tot;
}

// ---------------- fused gather + selfloop + bias, F=64 (2 nodes/warp, unroll 8) ---------
__global__ __launch_bounds__(256)
void k_gather64(const __half* __restrict__ xw, const float* __restrict__ b,
                float* __restrict__ out) {
    int warp = (blockIdx.x * blockDim.x + threadIdx.x) >> 5;
    int lane = threadIdx.x & 31;
    int w = warp * 2 + (lane >> 4);
    if (w >= N) return;
    int c = (lane & 15) * 4;

    float4 b0 = *(const float4*)(b + 0 * FOUT + c);
    float4 b1 = *(const float4*)(b + 1 * FOUT + c);
    float4 b2 = *(const float4*)(b + 2 * FOUT + c);
    float4 tot = make_float4(b0.x + b1.x + b2.x, b0.y + b1.y + b2.y,
                             b0.z + b1.z + b2.z, b0.w + b1.w + b2.w);

#pragma unroll
    for (int r = 0; r < R; r++) {
        const int bin = r * N + w;
        const __half* base = xw + (size_t)r * N * FOUT;
        float4 a = make_float4(0.f, 0.f, 0.f, 0.f);
        int j0 = g_off[bin], j1 = g_off[bin + 1];
        int j = j0;
        for (; j + 8 <= j1; j += 8) {
            int s[8];
#pragma unroll
            for (int p = 0; p < 8; p++) s[p] = __ldg(&g_eidx[j + p]);
            uint2 u[8];
#pragma unroll
            for (int p = 0; p < 8; p++)
                u[p] = *(const uint2*)(base + (size_t)s[p] * FOUT + c);
#pragma unroll
            for (int p = 0; p < 8; p++) {
                float2 f0 = __half22float2(*reinterpret_cast<__half2*>(&u[p].x));
                float2 f1 = __half22float2(*reinterpret_cast<__half2*>(&u[p].y));
                a.x += f0.x; a.y += f0.y; a.z += f1.x; a.w += f1.y;
            }
        }
        for (; j < j1; j++) {
            int s = __ldg(&g_eidx[j]);
            uint2 u = *(const uint2*)(base + (size_t)s * FOUT + c);
            float2 f0 = __half22float2(*reinterpret_cast<__half2*>(&u.x));
            float2 f1 = __half22float2(*reinterpret_cast<__half2*>(&u.y));
            a.x += f0.x; a.y += f0.y; a.z += f1.x; a.w += f1.y;
        }
        {
            uint2 u = *(const uint2*)(base + (size_t)w * FOUT + c);
            float2 f0 = __half22float2(*reinterpret_cast<__half2*>(&u.x));
            float2 f1 = __half22float2(*reinterpret_cast<__half2*>(&u.y));
            a.x += f0.x; a.y += f0.y; a.z += f1.x; a.w += f1.y;
        }
        float ri = g_rsi[bin];
        tot.x = fmaf(ri, a.x, tot.x); tot.y = fmaf(ri, a.y, tot.y);
        tot.z = fmaf(ri, a.z, tot.z); tot.w = fmaf(ri, a.w, tot.w);
    }
    *(float4*)(out + (size_t)w * FOUT + c) = tot;
}

// ---------------- launch ----------------
extern "C" void kernel_launch(void* const* d_in, const int* in_sizes, int n_in,
                              void* d_out, int out_size) {
    const float* x   = (const float*)d_in[0];
    const int*   src = (const int*)d_in[1];
    const int*   dst = (const int*)d_in[2];
    const float* W1  = (const float*)d_in[3];
    const float* b1  = (const float*)d_in[4];
    const float* W2  = (const float*)d_in[5];
    const float* b2  = (const float*)d_in[6];
    float* out = (float*)d_out;

    __half *xw1, *xw2;
    float *acc;
    int *dego, *degi;
    cudaGetSymbolAddress((void**)&xw1, g_xw1h);
    cudaGetSymbolAddress((void**)&acc, g_acc);
    cudaGetSymbolAddress((void**)&xw2, g_xw2h);
    cudaGetSymbolAddress((void**)&dego, g_dego);
    cudaGetSymbolAddress((void**)&degi, g_degi);

    const bool fork = (g_s1 != nullptr && g_evA != nullptr && g_evB != nullptr);
    cudaStream_t sb = fork ? g_s1 : (cudaStream_t)0;

    // Fork the side stream FROM the capture-origin stream (required for
    // stream capture: side-stream work must be downstream of an event
    // recorded in the captured stream).
    if (fork) {
        cudaEventRecord(g_evA, 0);
        cudaStreamWaitEvent(sb, g_evA, 0);
    }

    // side pipeline: in-degree -> CSR -> rsi (depends only on dst)
    cudaMemsetAsync(degi, 0, RN * sizeof(int), sb);
    k_degi<<<(RE + 255) / 256, 256, 0, sb>>>(dst);
    k_scan1<<<NSCAN, SCAN_BLK, 0, sb>>>();
    k_scan23<<<NSCAN, SCAN_BLK, 0, sb>>>();
    k_fill<<<(RE + 255) / 256, 256, 0, sb>>>(src, dst);
    k_rsi<<<(RN + 255) / 256, 256, 0, sb>>>();
    if (fork) cudaEventRecord(g_evB, sb);

    // main pipeline: out-degree -> rso -> GEMM1 (depends only on src, x)
    cudaMemsetAsync(dego, 0, RN * sizeof(int), 0);
    k_dego<<<(RE + 255) / 256, 256>>>(src);
    k_rso<<<(RN + 255) / 256, 256>>>();
    dim3 gg((N + 127) / 128, R);
    gemm_tc128<false><<<gg, 256>>>(x, W1, xw1, N);

    // join: gathers need CSR + rsi
    if (fork) cudaStreamWaitEvent((cudaStream_t)0, g_evB, 0);
    k_gather128<<<(N * 32 + 255) / 256, 256>>>(xw1, b1, acc);

    // layer 2
    gemm_tc64<true><<<gg, 256>>>(acc, W2, xw2, N);
    k_gather64<<<(N * 16 + 255) / 256, 256>>>(xw2, b2, out);
}

// round 11
// speedup vs baseline: 1.1198x; 1.0106x over previous
#include <cuda_runtime.h>
#include <cuda_fp16.h>
#include <cstdint>

// Problem constants (fixed by the dataset)
constexpr int N  = 50000;
constexpr int E  = 800000;
constexpr int R  = 3;
constexpr int FHID = 128;
constexpr int FOUT = 64;
constexpr int RN = R * N;
constexpr int RE = R * E;

constexpr int SCAN_BLK = 512;
constexpr int NSCAN = (RN + SCAN_BLK - 1) / SCAN_BLK;   // 293
static_assert(E % 4 == 0, "int4 edge batching requires E % 4 == 0");

// Scratch (device globals; no allocation allowed)
__device__ int    g_dego[RN];                       // edge-only out-degree
__device__ int    g_degi[RN];                       // edge-only in-degree
__device__ float  g_rso[RN];
__device__ float  g_rsi[RN];
__device__ int    g_off[RN + 1];
__device__ int    g_cur[RN];
__device__ int    g_part[RN];
__device__ int    g_bsum[SCAN_BLK];
__device__ int    g_eidx[RE];                       // CSR: src per (rel,dst)-bin
__device__ __half g_xw1h[(size_t)R * N * FHID];     // 38.4 MB (pre-scaled by rso)
__device__ float  g_acc[(size_t)N * FHID];          // 25.6 MB
__device__ __half g_xw2h[(size_t)R * N * FOUT];     // 19.2 MB (pre-scaled by rso)

// Side stream + events (host objects, created at load).
static cudaStream_t g_s1 = nullptr;
static cudaEvent_t  g_evA = nullptr, g_evB = nullptr;
namespace {
struct StreamInit {
    StreamInit() {
        cudaStreamCreateWithFlags(&g_s1, cudaStreamNonBlocking);
        cudaEventCreateWithFlags(&g_evA, cudaEventDisableTiming);
        cudaEventCreateWithFlags(&g_evB, cudaEventDisableTiming);
    }
} g_streaminit;
}

// ---------------- degrees: 4 edges/thread via int4 ----------------
__global__ void k_deg_count(const int4* __restrict__ src4, const int4* __restrict__ dst4) {
    int i = blockIdx.x * blockDim.x + threadIdx.x;
    if (i < RE / 4) {
        int base = ((i * 4) / E) * N;   // all 4 edges share the relation (E % 4 == 0)
        int4 s = __ldg(&src4[i]);
        int4 d = __ldg(&dst4[i]);
        atomicAdd(&g_dego[base + s.x], 1);
        atomicAdd(&g_dego[base + s.y], 1);
        atomicAdd(&g_dego[base + s.z], 1);
        atomicAdd(&g_dego[base + s.w], 1);
        atomicAdd(&g_degi[base + d.x], 1);
        atomicAdd(&g_degi[base + d.y], 1);
        atomicAdd(&g_degi[base + d.z], 1);
        atomicAdd(&g_degi[base + d.w], 1);
    }
}

// rsqrt of (degree + self-loop); both factors in one pass
__global__ void k_rso() {
    int i = blockIdx.x * blockDim.x + threadIdx.x;
    if (i < RN) {
        g_rso[i] = rsqrtf((float)(g_dego[i] + 1));
        g_rsi[i] = rsqrtf((float)(g_degi[i] + 1));
    }
}

// ---------------- CSR build ----------------
__global__ __launch_bounds__(SCAN_BLK) void k_scan1() {
    __shared__ int s[SCAN_BLK];
    int t = threadIdx.x;
    int i = blockIdx.x * SCAN_BLK + t;
    int v = (i < RN) ? g_degi[i] : 0;
    s[t] = v;
    __syncthreads();
#pragma unroll
    for (int off = 1; off < SCAN_BLK; off <<= 1) {
        int u = (t >= off) ? s[t - off] : 0;
        __syncthreads();
        s[t] += u;
        __syncthreads();
    }
    if (i < RN) g_part[i] = s[t];
    if (t == SCAN_BLK - 1) g_bsum[blockIdx.x] = s[t];
}

__global__ __launch_bounds__(SCAN_BLK) void k_scan23() {
    __shared__ int s[SCAN_BLK];
    int t = threadIdx.x, bid = blockIdx.x;
    s[t] = (t < bid && t < NSCAN) ? g_bsum[t] : 0;
    __syncthreads();
#pragma unroll
    for (int off = SCAN_BLK / 2; off > 0; off >>= 1) {
        if (t < off) s[t] += s[t + off];
        __syncthreads();
    }
    int blockpref = s[0];
    int i = bid * SCAN_BLK + t;
    if (i < RN) {
        int excl = g_part[i] - g_degi[i] + blockpref;
        g_off[i] = excl;
        g_cur[i] = excl;
    }
    if (i == 0) g_off[RN] = RE;
}

// CSR fill: 4 edges/thread via int4
__global__ void k_fill(const int4* __restrict__ src4, const int4* __restrict__ dst4) {
    int i = blockIdx.x * blockDim.x + threadIdx.x;
    if (i < RE / 4) {
        int base = ((i * 4) / E) * N;
        int4 s = __ldg(&src4[i]);
        int4 d = __ldg(&dst4[i]);
        int p0 = atomicAdd(&g_cur[base + d.x], 1);
        int p1 = atomicAdd(&g_cur[base + d.y], 1);
        int p2 = atomicAdd(&g_cur[base + d.z], 1);
        int p3 = atomicAdd(&g_cur[base + d.w], 1);
        g_eidx[p0] = s.x;
        g_eidx[p1] = s.y;
        g_eidx[p2] = s.z;
        g_eidx[p3] = s.w;
    }
}

// ---------------- tf32 helpers ----------------
__device__ __forceinline__ uint32_t f2tf(float f) {
    uint32_t u;
    asm("cvt.rna.tf32.f32 %0, %1;" : "=r"(u) : "f"(f));
    return u;
}

__device__ __forceinline__ void mma_tf32(float* d,
        uint32_t a0, uint32_t a1, uint32_t a2, uint32_t a3,
        uint32_t b0, uint32_t b1) {
    asm volatile(
        "mma.sync.aligned.m16n8k8.row.col.f32.tf32.tf32.f32 "
        "{%0,%1,%2,%3}, {%4,%5,%6,%7}, {%8,%9}, {%0,%1,%2,%3};"
        : "+f"(d[0]), "+f"(d[1]), "+f"(d[2]), "+f"(d[3])
        : "r"(a0), "r"(a1), "r"(a2), "r"(a3), "r"(b0), "r"(b1));
}

// ---------------- tf32 GEMM F=128 -> fp16 out, pre-scaled by rso ----------------
template<bool RELU>
__global__ __launch_bounds__(256)
void gemm_tc128(const float* __restrict__ A, const float* __restrict__ Wb,
                __half* __restrict__ Cb, int nrows) {
    constexpr int K = 128, BK = 32;
    const int r = blockIdx.y;
    const float* B = Wb + (size_t)r * K * 128;
    __half* C = Cb + (size_t)r * nrows * 128;
    const int row0 = blockIdx.x * 128;
    const int t = threadIdx.x;
    const int warp = t >> 5, lane = t & 31;
    const int qr = lane >> 2, qc = lane & 3;
    const int wm = (warp & 3) * 32;
    const int wn = (warp >> 2) * 64;

    __shared__ uint32_t sA[128][BK + 4];
    __shared__ uint32_t sB[BK][128 + 8];

    float acc[2][8][4];
#pragma unroll
    for (int i = 0; i < 2; i++)
#pragma unroll
        for (int j = 0; j < 8; j++)
#pragma unroll
            for (int q = 0; q < 4; q++) acc[i][j][q] = 0.f;

    const int am = t >> 1;
    const int ak = (t & 1) * 16;
    const int bkr = t >> 3;
    const int bnc = (t & 7) * 16;

    for (int k0 = 0; k0 < K; k0 += BK) {
        {
            int grow = row0 + am;
#pragma unroll
            for (int q = 0; q < 4; q++) {
                float4 v = make_float4(0.f, 0.f, 0.f, 0.f);
                if (grow < nrows)
                    v = *(const float4*)(A + (size_t)grow * K + k0 + ak + q * 4);
                if (RELU) {
                    v.x = fmaxf(v.x, 0.f); v.y = fmaxf(v.y, 0.f);
                    v.z = fmaxf(v.z, 0.f); v.w = fmaxf(v.w, 0.f);
                }
                uint4 u = make_uint4(f2tf(v.x), f2tf(v.y), f2tf(v.z), f2tf(v.w));
                *(uint4*)&sA[am][ak + q * 4] = u;
            }
        }
        {
#pragma unroll
            for (int q = 0; q < 4; q++) {
                float4 v = *(const float4*)(B + (size_t)(k0 + bkr) * 128 + bnc + q * 4);
                uint4 u = make_uint4(f2tf(v.x), f2tf(v.y), f2tf(v.z), f2tf(v.w));
                *(uint4*)&sB[bkr][bnc + q * 4] = u;
            }
        }
        __syncthreads();
#pragma unroll
        for (int kf = 0; kf < 4; kf++) {
            const int kb = kf * 8;
            uint32_t a[2][4];
#pragma unroll
            for (int mf = 0; mf < 2; mf++) {
                int rr = wm + mf * 16 + qr;
                a[mf][0] = sA[rr][kb + qc];
                a[mf][1] = sA[rr + 8][kb + qc];
                a[mf][2] = sA[rr][kb + qc + 4];
                a[mf][3] = sA[rr + 8][kb + qc + 4];
            }
#pragma unroll
            for (int nf = 0; nf < 8; nf++) {
                int nn = wn + nf * 8 + qr;
                uint32_t b0 = sB[kb + qc][nn];
                uint32_t b1 = sB[kb + qc + 4][nn];
                mma_tf32(acc[0][nf], a[0][0], a[0][1], a[0][2], a[0][3], b0, b1);
                mma_tf32(acc[1][nf], a[1][0], a[1][1], a[1][2], a[1][3], b0, b1);
            }
        }
        __syncthreads();
    }
#pragma unroll
    for (int mf = 0; mf < 2; mf++) {
        int r0g = row0 + wm + mf * 16 + qr;
        int r1g = r0g + 8;
        float s0 = (r0g < nrows) ? g_rso[r * N + r0g] : 0.f;
        float s1 = (r1g < nrows) ? g_rso[r * N + r1g] : 0.f;
#pragma unroll
        for (int nf = 0; nf < 8; nf++) {
            int col = wn + nf * 8 + qc * 2;
            if (r0g < nrows)
                *(__half2*)(C + (size_t)r0g * 128 + col) =
                    __floats2half2_rn(acc[mf][nf][0] * s0, acc[mf][nf][1] * s0);
            if (r1g < nrows)
                *(__half2*)(C + (size_t)r1g * 128 + col) =
                    __floats2half2_rn(acc[mf][nf][2] * s1, acc[mf][nf][3] * s1);
        }
    }
}

// ---------------- tf32 GEMM F=64 -> fp16 out, pre-scaled by rso ----------------
template<bool RELU>
__global__ __launch_bounds__(256)
void gemm_tc64(const float* __restrict__ A, const float* __restrict__ Wb,
               __half* __restrict__ Cb, int nrows) {
    constexpr int K = 128, BK = 32;
    const int r = blockIdx.y;
    const float* B = Wb + (size_t)r * K * 64;
    __half* C = Cb + (size_t)r * nrows * 64;
    const int row0 = blockIdx.x * 128;
    const int t = threadIdx.x;
    const int warp = t >> 5, lane = t & 31;
    const int qr = lane >> 2, qc = lane & 3;
    const int wm = (warp & 3) * 32;
    const int wn = (warp >> 2) * 32;

    __shared__ uint32_t sA[128][BK + 4];
    __shared__ uint32_t sB[BK][64 + 8];

    float acc[2][4][4];
#pragma unroll
    for (int i = 0; i < 2; i++)
#pragma unroll
        for (int j = 0; j < 4; j++)
#pragma unroll
            for (int q = 0; q < 4; q++) acc[i][j][q] = 0.f;

    const int am = t >> 1;
    const int ak = (t & 1) * 16;
    const int bkrow = t >> 3;
    const int bncol = (t & 7) * 8;

    for (int k0 = 0; k0 < K; k0 += BK) {
        {
            int grow = row0 + am;
#pragma unroll
            for (int q = 0; q < 4; q++) {
                float4 v = make_float4(0.f, 0.f, 0.f, 0.f);
                if (grow < nrows)
                    v = *(const float4*)(A + (size_t)grow * K + k0 + ak + q * 4);
                if (RELU) {
                    v.x = fmaxf(v.x, 0.f); v.y = fmaxf(v.y, 0.f);
                    v.z = fmaxf(v.z, 0.f); v.w = fmaxf(v.w, 0.f);
                }
                uint4 u = make_uint4(f2tf(v.x), f2tf(v.y), f2tf(v.z), f2tf(v.w));
                *(uint4*)&sA[am][ak + q * 4] = u;
            }
        }
        {
#pragma unroll
            for (int q = 0; q < 2; q++) {
                float4 v = *(const float4*)(B + (size_t)(k0 + bkrow) * 64 + bncol + q * 4);
                uint4 u = make_uint4(f2tf(v.x), f2tf(v.y), f2tf(v.z), f2tf(v.w));
                *(uint4*)&sB[bkrow][bncol + q * 4] = u;
            }
        }
        __syncthreads();
#pragma unroll
        for (int kf = 0; kf < 4; kf++) {
            const int kb = kf * 8;
            uint32_t a[2][4];
#pragma unroll
            for (int mf = 0; mf < 2; mf++) {
                int rr = wm + mf * 16 + qr;
                a[mf][0] = sA[rr][kb + qc];
                a[mf][1] = sA[rr + 8][kb + qc];
                a[mf][2] = sA[rr][kb + qc + 4];
                a[mf][3] = sA[rr + 8][kb + qc + 4];
            }
#pragma unroll
            for (int nf = 0; nf < 4; nf++) {
                int nn = wn + nf * 8 + qr;
                uint32_t b0 = sB[kb + qc][nn];
                uint32_t b1 = sB[kb + qc + 4][nn];
                mma_tf32(acc[0][nf], a[0][0], a[0][1], a[0][2], a[0][3], b0, b1);
                mma_tf32(acc[1][nf], a[1][0], a[1][1], a[1][2], a[1][3], b0, b1);
            }
        }
        __syncthreads();
    }
#pragma unroll
    for (int mf = 0; mf < 2; mf++) {
        int r0g = row0 + wm + mf * 16 + qr;
        int r1g = r0g + 8;
        float s0 = (r0g < nrows) ? g_rso[r * N + r0g] : 0.f;
        float s1 = (r1g < nrows) ? g_rso[r * N + r1g] : 0.f;
#pragma unroll
        for (int nf = 0; nf < 4; nf++) {
            int col = wn + nf * 8 + qc * 2;
            if (r0g < nrows)
                *(__half2*)(C + (size_t)r0g * 64 + col) =
                    __floats2half2_rn(acc[mf][nf][0] * s0, acc[mf][nf][1] * s0);
            if (r1g < nrows)
                *(__half2*)(C + (size_t)r1g * 64 + col) =
                    __floats2half2_rn(acc[mf][nf][2] * s1, acc[mf][nf][3] * s1);
        }
    }
}

// ---------------- fused gather + selfloop + bias, F=128 (fp16 pre-scaled, unroll 8) -----
__global__ __launch_bounds__(256)
void k_gather128(const __half* __restrict__ xw, const float* __restrict__ b,
                 float* __restrict__ out) {
    int w = (blockIdx.x * blockDim.x + threadIdx.x) >> 5;
    int lane = threadIdx.x & 31;
    if (w >= N) return;
    int c = lane * 4;

    float4 b0 = *(const float4*)(b + 0 * FHID + c);
    float4 b1 = *(const float4*)(b + 1 * FHID + c);
    float4 b2 = *(const float4*)(b + 2 * FHID + c);
    float4 tot = make_float4(b0.x + b1.x + b2.x, b0.y + b1.y + b2.y,
                             b0.z + b1.z + b2.z, b0.w + b1.w + b2.w);

#pragma unroll
    for (int r = 0; r < R; r++) {
        const int bin = r * N + w;
        const __half* base = xw + (size_t)r * N * FHID;
        float4 a = make_float4(0.f, 0.f, 0.f, 0.f);
        int j0 = g_off[bin], j1 = g_off[bin + 1];
        int j = j0;
        for (; j + 8 <= j1; j += 8) {
            int s[8];
#pragma unroll
            for (int p = 0; p < 8; p++) s[p] = __ldg(&g_eidx[j + p]);
            uint2 u[8];
#pragma unroll
            for (int p = 0; p < 8; p++)
                u[p] = *(const uint2*)(base + (size_t)s[p] * FHID + c);
#pragma unroll
            for (int p = 0; p < 8; p++) {
                float2 f0 = __half22float2(*reinterpret_cast<__half2*>(&u[p].x));
                float2 f1 = __half22float2(*reinterpret_cast<__half2*>(&u[p].y));
                a.x += f0.x; a.y += f0.y; a.z += f1.x; a.w += f1.y;
            }
        }
        for (; j < j1; j++) {
            int s = __ldg(&g_eidx[j]);
            uint2 u = *(const uint2*)(base + (size_t)s * FHID + c);
            float2 f0 = __half22float2(*reinterpret_cast<__half2*>(&u.x));
            float2 f1 = __half22float2(*reinterpret_cast<__half2*>(&u.y));
            a.x += f0.x; a.y += f0.y; a.z += f1.x; a.w += f1.y;
        }
        // self-loop: pre-scaled row already carries rso[w]
        {
            uint2 u = *(const uint2*)(base + (size_t)w * FHID + c);
            float2 f0 = __half22float2(*reinterpret_cast<__half2*>(&u.x));
            float2 f1 = __half22float2(*reinterpret_cast<__half2*>(&u.y));
            a.x += f0.x; a.y += f0.y; a.z += f1.x; a.w += f1.y;
        }
        float ri = g_rsi[bin];
        tot.x = fmaf(ri, a.x, tot.x); tot.y = fmaf(ri, a.y, tot.y);
        tot.z = fmaf(ri, a.z, tot.z); tot.w = fmaf(ri, a.w, tot.w);
    }
    *(float4*)(out + (size_t)w * FHID + c) = tot;
}

// ---------------- fused gather + selfloop + bias, F=64 (2 nodes/warp, unroll 8) ---------
__global__ __launch_bounds__(256)
void k_gather64(const __half* __restrict__ xw, const float* __restrict__ b,
                float* __restrict__ out) {
    int warp = (blockIdx.x * blockDim.x + threadIdx.x) >> 5;
    int lane = threadIdx.x & 31;
    int w = warp * 2 + (lane >> 4);
    if (w >= N) return;
    int c = (lane & 15) * 4;

    float4 b0 = *(const float4*)(b + 0 * FOUT + c);
    float4 b1 = *(const float4*)(b + 1 * FOUT + c);
    float4 b2 = *(const float4*)(b + 2 * FOUT + c);
    float4 tot = make_float4(b0.x + b1.x + b2.x, b0.y + b1.y + b2.y,
                             b0.z + b1.z + b2.z, b0.w + b1.w + b2.w);

#pragma unroll
    for (int r = 0; r < R; r++) {
        const int bin = r * N + w;
        const __half* base = xw + (size_t)r * N * FOUT;
        float4 a = make_float4(0.f, 0.f, 0.f, 0.f);
        int j0 = g_off[bin], j1 = g_off[bin + 1];
        int j = j0;
        for (; j + 8 <= j1; j += 8) {
            int s[8];
#pragma unroll
            for (int p = 0; p < 8; p++) s[p] = __ldg(&g_eidx[j + p]);
            uint2 u[8];
#pragma unroll
            for (int p = 0; p < 8; p++)
                u[p] = *(const uint2*)(base + (size_t)s[p] * FOUT + c);
#pragma unroll
            for (int p = 0; p < 8; p++) {
                float2 f0 = __half22float2(*reinterpret_cast<__half2*>(&u[p].x));
                float2 f1 = __half22float2(*reinterpret_cast<__half2*>(&u[p].y));
                a.x += f0.x; a.y += f0.y; a.z += f1.x; a.w += f1.y;
            }
        }
        for (; j < j1; j++) {
            int s = __ldg(&g_eidx[j]);
            uint2 u = *(const uint2*)(base + (size_t)s * FOUT + c);
            float2 f0 = __half22float2(*reinterpret_cast<__half2*>(&u.x));
            float2 f1 = __half22float2(*reinterpret_cast<__half2*>(&u.y));
            a.x += f0.x; a.y += f0.y; a.z += f1.x; a.w += f1.y;
        }
        {
            uint2 u = *(const uint2*)(base + (size_t)w * FOUT + c);
            float2 f0 = __half22float2(*reinterpret_cast<__half2*>(&u.x));
            float2 f1 = __half22float2(*reinterpret_cast<__half2*>(&u.y));
            a.x += f0.x; a.y += f0.y; a.z += f1.x; a.w += f1.y;
        }
        float ri = g_rsi[bin];
        tot.x = fmaf(ri, a.x, tot.x); tot.y = fmaf(ri, a.y, tot.y);
        tot.z = fmaf(ri, a.z, tot.z); tot.w = fmaf(ri, a.w, tot.w);
    }
    *(float4*)(out + (size_t)w * FOUT + c) = tot;
}

// ---------------- launch ----------------
extern "C" void kernel_launch(void* const* d_in, const int* in_sizes, int n_in,
                              void* d_out, int out_size) {
    const float* x   = (const float*)d_in[0];
    const int*   src = (const int*)d_in[1];
    const int*   dst = (const int*)d_in[2];
    const float* W1  = (const float*)d_in[3];
    const float* b1  = (const float*)d_in[4];
    const float* W2  = (const float*)d_in[5];
    const float* b2  = (const float*)d_in[6];
    float* out = (float*)d_out;

    __half *xw1, *xw2;
    float *acc;
    int *dego, *degi;
    cudaGetSymbolAddress((void**)&xw1, g_xw1h);
    cudaGetSymbolAddress((void**)&acc, g_acc);
    cudaGetSymbolAddress((void**)&xw2, g_xw2h);
    cudaGetSymbolAddress((void**)&dego, g_dego);
    cudaGetSymbolAddress((void**)&degi, g_degi);

    const bool fork = (g_s1 != nullptr && g_evA != nullptr && g_evB != nullptr);
    cudaStream_t sb = fork ? g_s1 : (cudaStream_t)0;

    const int4* src4 = (const int4*)src;
    const int4* dst4 = (const int4*)dst;
    const int NB4 = (RE / 4 + 255) / 256;

    // degrees (main stream, combined; 4 edges/thread)
    cudaMemsetAsync(dego, 0, RN * sizeof(int), 0);
    cudaMemsetAsync(degi, 0, RN * sizeof(int), 0);
    k_deg_count<<<NB4, 256>>>(src4, dst4);

    // fork: CSR build (scan + fill) on side stream, overlapped with rso + GEMM1
    if (fork) {
        cudaEventRecord(g_evA, 0);
        cudaStreamWaitEvent(sb, g_evA, 0);
    }
    k_scan1<<<NSCAN, SCAN_BLK, 0, sb>>>();
    k_scan23<<<NSCAN, SCAN_BLK, 0, sb>>>();
    k_fill<<<NB4, 256, 0, sb>>>(src4, dst4);
    if (fork) cudaEventRecord(g_evB, sb);

    // main stream: rso/rsi -> GEMM1 (needs only degrees, not CSR)
    k_rso<<<(RN + 255) / 256, 256>>>();
    dim3 gg((N + 127) / 128, R);
    gemm_tc128<false><<<gg, 256>>>(x, W1, xw1, N);

    // join: gathers need the CSR
    if (fork) cudaStreamWaitEvent((cudaStream_t)0, g_evB, 0);
    k_gather128<<<(N * 32 + 255) / 256, 256>>>(xw1, b1, acc);

    // layer 2
    gemm_tc64<true><<<gg, 256>>>(acc, W2, xw2, N);
    k_gather64<<<(N * 16 + 255) / 256, 256>>>(xw2, b2, out);
}